// round 16
// baseline (speedup 1.0000x reference)
#include <cuda_runtime.h>
#include <cuda_fp16.h>
#include <cstdint>

// ---------------------------------------------------------------------------
// S5 layer:  B=8, L=4096, H=512, P=256
// Tensor path: warp-level mma.sync fp16 (HMMA) — tcgen05 unavailable (ptxas
// targets plain sm_103).
// Precision: 2-pass fp16 split  A@B ~= Ahi@Bhi + Alo@Bhi  (verified 2.1e-4).
// W1 pre-scaled by 2^8 (fp16 normal range), compensated in GEMM1 epilogue.
// R13: warp tile stays 32x64 (64x64 spilled). R15: 4-stage ring ~neutral.
// R16: software-pipelined fragments — ldmatrix for k16+1 issued before the
// MMAs of k16 (hides LDSM latency at 2 warps/SMSP), and hi/lo MMA passes
// separated so same-acc RAW pairs are >=16 instructions apart.
// ---------------------------------------------------------------------------

#define BDIM 8
#define LDIM 4096
#define HDIM 512
#define PDIM 256
#define BL   (BDIM * LDIM)          // 32768 tokens
#define NCH  64
#define TCH  (LDIM / NCH)           // 64
#define OUT_ELEMS ((size_t)BL * HDIM)
#define W1_SCALE     256.0f
#define W1_SCALE_INV (1.0f / 256.0f)

// -------------------- device scratch ---------------------------------------
__device__ float2 g_Bu[(size_t)BL * PDIM];          // 64 MB (Bu f32)
__device__ float2 g_end[BDIM * NCH * PDIM];
__device__ float2 g_carry[BDIM * NCH * PDIM];
__device__ __half g_Ahi[(size_t)BL * 512];          // u split hi
__device__ __half g_Alo[(size_t)BL * 512];          // u split lo
__device__ __half g_Xhi[(size_t)BL * 512];          // xs split hi (real view)
__device__ __half g_Xlo[(size_t)BL * 512];
__device__ __half g_W1Thi[512 * 512];               // [n][k=h], scaled 2^8
__device__ __half g_W2Thi[512 * 512];               // [h][k=2p|2p+1]
__device__ float2 g_lambda[PDIM];
__device__ float2 g_f[PDIM];
__device__ float2 g_aT[PDIM];

// -------------------- PTX helpers ------------------------------------------
__device__ __forceinline__ uint32_t smem_u32(const void* p) {
    uint32_t a;
    asm("{ .reg .u64 t; cvta.to.shared.u64 t, %1; cvt.u32.u64 %0, t; }"
        : "=r"(a) : "l"(p));
    return a;
}
__device__ __forceinline__ void cp16(uint32_t saddr, const void* gptr) {
    uint64_t g;
    asm("cvta.to.global.u64 %0, %1;" : "=l"(g) : "l"(gptr));
    asm volatile("cp.async.cg.shared.global [%0], [%1], 16;"
                 :: "r"(saddr), "l"(g) : "memory");
}
__device__ __forceinline__ void cp_commit() {
    asm volatile("cp.async.commit_group;" ::: "memory");
}
template <int N>
__device__ __forceinline__ void cp_wait() {
    asm volatile("cp.async.wait_group %0;" :: "n"(N) : "memory");
}
__device__ __forceinline__ void ldm_x4(uint32_t* r, uint32_t addr) {
    asm volatile("ldmatrix.sync.aligned.m8n8.x4.shared.b16 {%0,%1,%2,%3}, [%4];"
                 : "=r"(r[0]), "=r"(r[1]), "=r"(r[2]), "=r"(r[3]) : "r"(addr));
}
__device__ __forceinline__ void mma16816(float* c, const uint32_t* a, const uint32_t* b) {
    asm volatile(
        "mma.sync.aligned.m16n8k16.row.col.f32.f16.f16.f32 "
        "{%0,%1,%2,%3}, {%4,%5,%6,%7}, {%8,%9}, {%0,%1,%2,%3};"
        : "+f"(c[0]), "+f"(c[1]), "+f"(c[2]), "+f"(c[3])
        : "r"(a[0]), "r"(a[1]), "r"(a[2]), "r"(a[3]), "r"(b[0]), "r"(b[1]));
}
__device__ __forceinline__ uint32_t sw128(uint32_t bo) {
    return bo ^ ((bo >> 3) & 0x70);
}

// -------------------- math helpers -----------------------------------------
__device__ __forceinline__ float2 cfma(float2 a, float2 x, float2 v) {
    float2 r;
    r.x = fmaf(a.x, x.x, fmaf(-a.y, x.y, v.x));
    r.y = fmaf(a.x, x.y, fmaf(a.y, x.x, v.y));
    return r;
}

// -------------------- setup kernels ----------------------------------------
__global__ void k_setup_small(const float* __restrict__ Lre,
                              const float* __restrict__ Lim,
                              const float* __restrict__ lstep) {
    int p = threadIdx.x;
    if (p >= PDIM) return;
    double lr = (double)Lre[p], li = (double)Lim[p];
    double dt = exp((double)lstep[p]);
    double mag = exp(lr * dt), ang = li * dt;
    double lbr = mag * cos(ang), lbi = mag * sin(ang);
    g_lambda[p] = make_float2((float)lbr, (float)lbi);
    double den = lr * lr + li * li;
    double nr = lbr - 1.0, ni = lbi;
    g_f[p] = make_float2((float)((nr * lr + ni * li) / den),
                         (float)((ni * lr - nr * li) / den));
    double magT = exp(lr * dt * (double)TCH);
    double angT = li * dt * (double)TCH;
    g_aT[p] = make_float2((float)(magT * cos(angT)), (float)(magT * sin(angT)));
}

__global__ void k_setup_weights(const float* __restrict__ Bw,   // (P,H,2)
                                const float* __restrict__ Cw) { // (H,P,2)
    int idx = blockIdx.x * 256 + threadIdx.x;   // 0..262143
    // W1T[n][h] = (n odd) ? Im(f_p * B~[p,h]) : Re(f_p * B~[p,h]),  p=n/2
    // scaled by 2^8 for fp16 normal range (compensated in GEMM1 epilogue)
    {
        int n = idx >> 9, h = idx & 511, p = n >> 1;
        float2 f = g_f[p];
        float b0 = Bw[p * 1024 + h * 2 + 0];
        float b1 = Bw[p * 1024 + h * 2 + 1];
        float w = (n & 1) ? (f.x * b1 + f.y * b0) : (f.x * b0 - f.y * b1);
        g_W1Thi[idx] = __float2half(w * W1_SCALE);
    }
    // W2T[h][k] : k=2p -> 2*C_re[h,p],  k=2p+1 -> -2*C_im[h,p]
    {
        int h = idx >> 9, k = idx & 511, p = k >> 1;
        float c0 = Cw[h * 512 + p * 2 + 0];
        float c1 = Cw[h * 512 + p * 2 + 1];
        float w = (k & 1) ? (-2.0f * c1) : (2.0f * c0);
        g_W2Thi[idx] = __float2half(w);
    }
}

__global__ void k_split_u(const float* __restrict__ u) {
    size_t i = (size_t)blockIdx.x * 256 + threadIdx.x;   // x4 floats each
    float4 v = ((const float4*)u)[i];
    __half h0 = __float2half(v.x), h1 = __float2half(v.y);
    __half h2 = __float2half(v.z), h3 = __float2half(v.w);
    __half2 a01, a23;
    a01.x = h0; a01.y = h1; a23.x = h2; a23.y = h3;
    ((__half2*)g_Ahi)[2 * i + 0] = a01;
    ((__half2*)g_Ahi)[2 * i + 1] = a23;
    __half2 l01, l23;
    l01.x = __float2half(v.x - __half2float(h0));
    l01.y = __float2half(v.y - __half2float(h1));
    l23.x = __float2half(v.z - __half2float(h2));
    l23.y = __float2half(v.w - __half2float(h3));
    ((__half2*)g_Alo)[2 * i + 0] = l01;
    ((__half2*)g_Alo)[2 * i + 1] = l23;
}

// -------------------- mma.sync GEMM ----------------------------------------
// CTA tile 128(M) x 128(N); 8 warps in 4(M) x 2(N); warp tile 32 x 64.
// K streamed in 64-elem chunks (8 chunks). Stage: Ahi 16K | Alo 16K |
// Bhi 16K = 48KB; 4-stage ring; fragments software-pipelined across k16.
#define KCHN        64
#define NCHUNK      8
#define ST_AH       0
#define ST_AL       16384
#define ST_BH       32768
#define STAGE_BYTES 49152
#define NSTAGE      4
#define GEMM_SMEM   (NSTAGE * STAGE_BYTES)

template <int EPI>
__global__ __launch_bounds__(256, 1)
void k_mma_gemm(float* __restrict__ OutExt,
                const float* __restrict__ U,
                const float* __restrict__ Dv) {
    const __half* Ahi = EPI ? g_Xhi : g_Ahi;
    const __half* Alo = EPI ? g_Xlo : g_Alo;
    const __half* Bhi = EPI ? g_W2Thi : g_W1Thi;
    float* Out = EPI ? OutExt : (float*)g_Bu;

    extern __shared__ char smem[];
    const uint32_t sbase = smem_u32(smem);
    const int tid = threadIdx.x;
    const int wid = tid >> 5, lane = tid & 31;
    const int warpM = wid & 3, warpN = wid >> 2;
    const int mBase = blockIdx.y * 128;
    const int nBase = blockIdx.x * 128;

    float acc[2][8][4];
#pragma unroll
    for (int mt = 0; mt < 2; mt++)
#pragma unroll
        for (int nt = 0; nt < 8; nt++)
#pragma unroll
            for (int j = 0; j < 4; j++) acc[mt][nt][j] = 0.0f;

    // ---- async load of one K-chunk into a stage (3 x 128rows x 128B) ----
    auto load_stage = [&](int stg, int c) {
        uint32_t sb = sbase + stg * STAGE_BYTES;
#pragma unroll
        for (int op = 0; op < 3; op++) {
            const char* g =
                (op == 0) ? (const char*)Ahi :
                (op == 1) ? (const char*)Alo : (const char*)Bhi;
            const int rb = (op < 2) ? mBase : nBase;
            const char* gbase = g + (size_t)rb * 1024 + (size_t)c * 128;
#pragma unroll
            for (int i = 0; i < 4; i++) {
                int idx = tid + i * 256;          // 0..1023
                int r = idx >> 3, q = idx & 7;
                uint32_t bo = (uint32_t)(r * 128 + q * 16);
                cp16(sb + op * 16384 + sw128(bo),
                     gbase + (size_t)r * 1024 + q * 16);
            }
        }
    };

    // prologue: chunks 0..2 into stages 0..2 (one commit group per chunk)
#pragma unroll
    for (int c = 0; c < 3; c++) {
        load_stage(c, c);
        cp_commit();
    }

    // fragment-address components (verified mapping from R9)
    const int rowA = ((lane >> 3) & 1) * 8 + (lane & 7);
    const int khA  = lane >> 4;                // 0/1 -> k-half
    const int rowB = ((lane >> 4) & 1) * 8 + (lane & 7);
    const int khB  = (lane >> 3) & 1;

    // double-buffered fragments (software pipeline across k16)
    uint32_t ah[2][2][4], al[2][2][4], bh[2][4][4];

    // fragment loaders for a given k16 into buffer `buf`
    auto ldA = [&](uint32_t sb, int k16, int buf) {
#pragma unroll
        for (int mt = 0; mt < 2; mt++) {
            int m0 = warpM * 32 + mt * 16;
            uint32_t bo = (uint32_t)((m0 + rowA) * 128 + k16 * 32 + khA * 16);
            uint32_t sw = sw128(bo);
            ldm_x4(ah[buf][mt], sb + ST_AH + sw);
            ldm_x4(al[buf][mt], sb + ST_AL + sw);
        }
    };
    auto ldB = [&](uint32_t sb, int k16, int buf) {
#pragma unroll
        for (int np = 0; np < 4; np++) {
            int n0 = warpN * 64 + np * 16;
            uint32_t bo = (uint32_t)((n0 + rowB) * 128 + k16 * 32 + khB * 16);
            ldm_x4(bh[buf][np], sb + ST_BH + sw128(bo));
        }
    };

    for (int c = 0; c < NCHUNK; c++) {
        // wait until chunk c's group has landed (tail: fewer groups remain)
        if (c + 2 < NCHUNK)      cp_wait<2>();
        else if (c + 1 < NCHUNK) cp_wait<1>();
        else                     cp_wait<0>();
        __syncthreads();   // stage c visible; stage (c+3)&3 free
        if (c + 3 < NCHUNK) {
            load_stage((c + 3) & 3, c + 3);
            cp_commit();
        }

        uint32_t sb = sbase + (c & 3) * STAGE_BYTES;

        // prime fragments for k16 = 0
        ldA(sb, 0, 0);
        ldB(sb, 0, 0);

#pragma unroll
        for (int k16 = 0; k16 < 4; k16++) {
            const int cur = k16 & 1, nxt = cur ^ 1;
            if (k16 < 3) {              // prefetch next k16's fragments
                ldA(sb, k16 + 1, nxt);
                ldB(sb, k16 + 1, nxt);
            }
            // hi pass: 16 independent MMAs
#pragma unroll
            for (int np = 0; np < 4; np++)
#pragma unroll
                for (int j = 0; j < 2; j++)
#pragma unroll
                    for (int mt = 0; mt < 2; mt++)
                        mma16816(acc[mt][np * 2 + j], ah[cur][mt],
                                 &bh[cur][np][2 * j]);
            // lo pass: 16 independent MMAs (>=16 instr from their hi pair)
#pragma unroll
            for (int np = 0; np < 4; np++)
#pragma unroll
                for (int j = 0; j < 2; j++)
#pragma unroll
                    for (int mt = 0; mt < 2; mt++)
                        mma16816(acc[mt][np * 2 + j], al[cur][mt],
                                 &bh[cur][np][2 * j]);
        }
    }

    // ---- epilogue: acc fragment -> gmem ----
    const int r0  = mBase + warpM * 32 + (lane >> 2);
    const int c00 = nBase + warpN * 64 + 2 * (lane & 3);
#pragma unroll
    for (int mt = 0; mt < 2; mt++) {
#pragma unroll
        for (int nt = 0; nt < 8; nt++) {
            int row = r0 + mt * 16;
            int col = c00 + nt * 8;
            float2 v0 = make_float2(acc[mt][nt][0], acc[mt][nt][1]);
            float2 v1 = make_float2(acc[mt][nt][2], acc[mt][nt][3]);
            if (EPI) {
                float2 dv = *(const float2*)(Dv + col);
                float2 u0 = *(const float2*)(U + (size_t)row * 512 + col);
                float2 u1 = *(const float2*)(U + (size_t)(row + 8) * 512 + col);
                v0.x = fmaf(dv.x, u0.x, v0.x); v0.y = fmaf(dv.y, u0.y, v0.y);
                v1.x = fmaf(dv.x, u1.x, v1.x); v1.y = fmaf(dv.y, u1.y, v1.y);
            } else {
                v0.x *= W1_SCALE_INV; v0.y *= W1_SCALE_INV;
                v1.x *= W1_SCALE_INV; v1.y *= W1_SCALE_INV;
            }
            *(float2*)(Out + (size_t)row * 512 + col) = v0;
            *(float2*)(Out + (size_t)(row + 8) * 512 + col) = v1;
        }
    }
}

// -------------------- scan (verified fp32 path) ----------------------------
__global__ void k_scan_end() {
    int g = blockIdx.x * 256 + threadIdx.x;
    int p = g & (PDIM - 1);
    int c = (g >> 8) & (NCH - 1);
    int b = g >> 14;
    float2 a = g_lambda[p];
    float2 e = make_float2(0.0f, 0.0f);
    const float2* src = g_Bu + ((size_t)(b * LDIM + c * TCH)) * PDIM + p;
#pragma unroll 4
    for (int j = 0; j < TCH; j++) e = cfma(a, e, src[(size_t)j * PDIM]);
    g_end[(b * NCH + c) * PDIM + p] = e;
}

__global__ void k_scan_carry() {
    int g = blockIdx.x * 256 + threadIdx.x;
    int p = g & (PDIM - 1);
    int b = g >> 8;
    float2 aT = g_aT[p];
    float2 carry = make_float2(0.0f, 0.0f);
    for (int c = 0; c < NCH; c++) {
        g_carry[(b * NCH + c) * PDIM + p] = carry;
        float2 e = g_end[(b * NCH + c) * PDIM + p];
        carry = cfma(aT, carry, e);
    }
}

// phase C: rescan with carry; emit xs as fp16 hi/lo splits + state
template <int STATE_MODE>
__global__ void k_scan_write(float* __restrict__ out_state) {
    int g = blockIdx.x * 256 + threadIdx.x;
    int p = g & (PDIM - 1);
    int c = (g >> 8) & (NCH - 1);
    int b = g >> 14;
    float2 a = g_lambda[p];
    float2 x = g_carry[(b * NCH + c) * PDIM + p];
    const size_t base = ((size_t)(b * LDIM + c * TCH)) * PDIM + p;
    const float2* buf = g_Bu + base;
    __half2* xh = (__half2*)g_Xhi + base;
    __half2* xl = (__half2*)g_Xlo + base;
#pragma unroll 4
    for (int j = 0; j < TCH; j++) {
        x = cfma(a, x, buf[(size_t)j * PDIM]);
        __half hr = __float2half(x.x);
        __half hi = __float2half(x.y);
        __half2 h; h.x = hr; h.y = hi;
        xh[(size_t)j * PDIM] = h;
        __half2 l;
        l.x = __float2half(x.x - __half2float(hr));
        l.y = __float2half(x.y - __half2float(hi));
        xl[(size_t)j * PDIM] = l;
    }
    if (c == NCH - 1) {
        if (STATE_MODE == 0) {
            out_state[b * PDIM + p] = x.x;
        } else {
            out_state[b * PDIM + p] = x.x;
            out_state[BDIM * PDIM + b * PDIM + p] = x.y;
        }
    }
}

// ---------------------------------------------------------------------------
extern "C" void kernel_launch(void* const* d_in, const int* in_sizes, int n_in,
                              void* d_out, int out_size) {
    const float* u   = (const float*)d_in[0];
    const float* Lre = (const float*)d_in[1];
    const float* Lim = (const float*)d_in[2];
    const float* Bw  = (const float*)d_in[3];
    const float* Cw  = (const float*)d_in[4];
    const float* Dv  = (const float*)d_in[5];
    const float* lst = (const float*)d_in[6];
    float* out = (float*)d_out;
    float* out_state = out + OUT_ELEMS;
    const long long state_floats = (long long)out_size - (long long)OUT_ELEMS;
    (void)in_sizes; (void)n_in;

    cudaFuncSetAttribute(k_mma_gemm<0>, cudaFuncAttributeMaxDynamicSharedMemorySize, GEMM_SMEM);
    cudaFuncSetAttribute(k_mma_gemm<1>, cudaFuncAttributeMaxDynamicSharedMemorySize, GEMM_SMEM);

    k_setup_small<<<1, 256>>>(Lre, Lim, lst);
    k_setup_weights<<<1024, 256>>>(Bw, Cw);
    k_split_u<<<16384, 256>>>(u);

    dim3 ggrid(4, BL / 128);   // (N tiles, M tiles) = (4, 256)
    k_mma_gemm<0><<<ggrid, 256, GEMM_SMEM>>>(nullptr, nullptr, nullptr);

    k_scan_end<<<(BDIM * NCH * PDIM) / 256, 256>>>();
    k_scan_carry<<<(BDIM * PDIM) / 256, 256>>>();
    if (state_floats == BDIM * PDIM) {
        k_scan_write<0><<<(BDIM * NCH * PDIM) / 256, 256>>>(out_state);
    } else {
        k_scan_write<1><<<(BDIM * NCH * PDIM) / 256, 256>>>(out_state);
    }

    k_mma_gemm<1><<<ggrid, 256, GEMM_SMEM>>>(out, u, Dv);
}

// round 17
// speedup vs baseline: 1.4393x; 1.4393x over previous
#include <cuda_runtime.h>
#include <cuda_fp16.h>
#include <cstdint>

// ---------------------------------------------------------------------------
// S5 layer:  B=8, L=4096, H=512, P=256
// Tensor path: warp-level mma.sync fp16 (HMMA) — tcgen05 unavailable (ptxas
// targets plain sm_103).
// R17 precision: PURE fp16 operands (1 pass, no lo-correction). Error model:
// adds A-truncation terms to the verified 2-pass error (2.086e-4) -> ~3e-4,
// threshold 1e-3. W1 pre-scaled by 2^8 (fp16 normal range), compensated in
// GEMM1 epilogue.
// R17 occupancy: acc is now 64 regs -> __launch_bounds__(256,2) = 2 CTA/SM
// = 4 warps/SMSP (R15/R16 showed 2 warps/SMSP cannot hide the latency chain).
// 3-stage x 32KB cp.async ring per CTA (2 CTAs fit the 227KB carveout).
// ---------------------------------------------------------------------------

#define BDIM 8
#define LDIM 4096
#define HDIM 512
#define PDIM 256
#define BL   (BDIM * LDIM)          // 32768 tokens
#define NCH  64
#define TCH  (LDIM / NCH)           // 64
#define OUT_ELEMS ((size_t)BL * HDIM)
#define W1_SCALE     256.0f
#define W1_SCALE_INV (1.0f / 256.0f)

// -------------------- device scratch ---------------------------------------
__device__ float2 g_Bu[(size_t)BL * PDIM];          // 64 MB (Bu f32)
__device__ float2 g_end[BDIM * NCH * PDIM];
__device__ float2 g_carry[BDIM * NCH * PDIM];
__device__ __half g_Ahi[(size_t)BL * 512];          // u as fp16
__device__ __half g_Xhi[(size_t)BL * 512];          // xs as fp16 (real view)
__device__ __half g_W1Thi[512 * 512];               // [n][k=h], scaled 2^8
__device__ __half g_W2Thi[512 * 512];               // [h][k=2p|2p+1]
__device__ float2 g_lambda[PDIM];
__device__ float2 g_f[PDIM];
__device__ float2 g_aT[PDIM];

// -------------------- PTX helpers ------------------------------------------
__device__ __forceinline__ uint32_t smem_u32(const void* p) {
    uint32_t a;
    asm("{ .reg .u64 t; cvta.to.shared.u64 t, %1; cvt.u32.u64 %0, t; }"
        : "=r"(a) : "l"(p));
    return a;
}
__device__ __forceinline__ void cp16(uint32_t saddr, const void* gptr) {
    uint64_t g;
    asm("cvta.to.global.u64 %0, %1;" : "=l"(g) : "l"(gptr));
    asm volatile("cp.async.cg.shared.global [%0], [%1], 16;"
                 :: "r"(saddr), "l"(g) : "memory");
}
__device__ __forceinline__ void cp_commit() {
    asm volatile("cp.async.commit_group;" ::: "memory");
}
template <int N>
__device__ __forceinline__ void cp_wait() {
    asm volatile("cp.async.wait_group %0;" :: "n"(N) : "memory");
}
__device__ __forceinline__ void ldm_x4(uint32_t* r, uint32_t addr) {
    asm volatile("ldmatrix.sync.aligned.m8n8.x4.shared.b16 {%0,%1,%2,%3}, [%4];"
                 : "=r"(r[0]), "=r"(r[1]), "=r"(r[2]), "=r"(r[3]) : "r"(addr));
}
__device__ __forceinline__ void mma16816(float* c, const uint32_t* a, const uint32_t* b) {
    asm volatile(
        "mma.sync.aligned.m16n8k16.row.col.f32.f16.f16.f32 "
        "{%0,%1,%2,%3}, {%4,%5,%6,%7}, {%8,%9}, {%0,%1,%2,%3};"
        : "+f"(c[0]), "+f"(c[1]), "+f"(c[2]), "+f"(c[3])
        : "r"(a[0]), "r"(a[1]), "r"(a[2]), "r"(a[3]), "r"(b[0]), "r"(b[1]));
}
__device__ __forceinline__ uint32_t sw128(uint32_t bo) {
    return bo ^ ((bo >> 3) & 0x70);
}

// -------------------- math helpers -----------------------------------------
__device__ __forceinline__ float2 cfma(float2 a, float2 x, float2 v) {
    float2 r;
    r.x = fmaf(a.x, x.x, fmaf(-a.y, x.y, v.x));
    r.y = fmaf(a.x, x.y, fmaf(a.y, x.x, v.y));
    return r;
}

// -------------------- setup kernels ----------------------------------------
__global__ void k_setup_small(const float* __restrict__ Lre,
                              const float* __restrict__ Lim,
                              const float* __restrict__ lstep) {
    int p = threadIdx.x;
    if (p >= PDIM) return;
    double lr = (double)Lre[p], li = (double)Lim[p];
    double dt = exp((double)lstep[p]);
    double mag = exp(lr * dt), ang = li * dt;
    double lbr = mag * cos(ang), lbi = mag * sin(ang);
    g_lambda[p] = make_float2((float)lbr, (float)lbi);
    double den = lr * lr + li * li;
    double nr = lbr - 1.0, ni = lbi;
    g_f[p] = make_float2((float)((nr * lr + ni * li) / den),
                         (float)((ni * lr - nr * li) / den));
    double magT = exp(lr * dt * (double)TCH);
    double angT = li * dt * (double)TCH;
    g_aT[p] = make_float2((float)(magT * cos(angT)), (float)(magT * sin(angT)));
}

__global__ void k_setup_weights(const float* __restrict__ Bw,   // (P,H,2)
                                const float* __restrict__ Cw) { // (H,P,2)
    int idx = blockIdx.x * 256 + threadIdx.x;   // 0..262143
    // W1T[n][h] = (n odd) ? Im(f_p * B~[p,h]) : Re(f_p * B~[p,h]),  p=n/2
    // scaled by 2^8 for fp16 normal range (compensated in GEMM1 epilogue)
    {
        int n = idx >> 9, h = idx & 511, p = n >> 1;
        float2 f = g_f[p];
        float b0 = Bw[p * 1024 + h * 2 + 0];
        float b1 = Bw[p * 1024 + h * 2 + 1];
        float w = (n & 1) ? (f.x * b1 + f.y * b0) : (f.x * b0 - f.y * b1);
        g_W1Thi[idx] = __float2half(w * W1_SCALE);
    }
    // W2T[h][k] : k=2p -> 2*C_re[h,p],  k=2p+1 -> -2*C_im[h,p]
    {
        int h = idx >> 9, k = idx & 511, p = k >> 1;
        float c0 = Cw[h * 512 + p * 2 + 0];
        float c1 = Cw[h * 512 + p * 2 + 1];
        float w = (k & 1) ? (-2.0f * c1) : (2.0f * c0);
        g_W2Thi[idx] = __float2half(w);
    }
}

__global__ void k_split_u(const float* __restrict__ u) {
    size_t i = (size_t)blockIdx.x * 256 + threadIdx.x;   // x4 floats each
    float4 v = ((const float4*)u)[i];
    __half2 a01, a23;
    a01.x = __float2half(v.x); a01.y = __float2half(v.y);
    a23.x = __float2half(v.z); a23.y = __float2half(v.w);
    ((__half2*)g_Ahi)[2 * i + 0] = a01;
    ((__half2*)g_Ahi)[2 * i + 1] = a23;
}

// -------------------- mma.sync GEMM ----------------------------------------
// CTA tile 128(M) x 128(N); 8 warps in 4(M) x 2(N); warp tile 32 x 64.
// K streamed in 64-elem chunks (8 chunks). Stage: Ah 16K | Bh 16K = 32KB;
// 3-stage ring (96KB smem), one barrier per chunk, 2 CTAs/SM.
#define KCHN        64
#define NCHUNK      8
#define ST_AH       0
#define ST_BH       16384
#define STAGE_BYTES 32768
#define NSTAGE      3
#define GEMM_SMEM   (NSTAGE * STAGE_BYTES)

template <int EPI>
__global__ __launch_bounds__(256, 2)
void k_mma_gemm(float* __restrict__ OutExt,
                const float* __restrict__ U,
                const float* __restrict__ Dv) {
    const __half* Ahi = EPI ? g_Xhi : g_Ahi;
    const __half* Bhi = EPI ? g_W2Thi : g_W1Thi;
    float* Out = EPI ? OutExt : (float*)g_Bu;

    extern __shared__ char smem[];
    const uint32_t sbase = smem_u32(smem);
    const int tid = threadIdx.x;
    const int wid = tid >> 5, lane = tid & 31;
    const int warpM = wid & 3, warpN = wid >> 2;
    const int mBase = blockIdx.y * 128;
    const int nBase = blockIdx.x * 128;

    float acc[2][8][4];
#pragma unroll
    for (int mt = 0; mt < 2; mt++)
#pragma unroll
        for (int nt = 0; nt < 8; nt++)
#pragma unroll
            for (int j = 0; j < 4; j++) acc[mt][nt][j] = 0.0f;

    // ---- async load of one K-chunk into a stage (2 x 128rows x 128B) ----
    auto load_stage = [&](int stg, int c) {
        uint32_t sb = sbase + stg * STAGE_BYTES;
#pragma unroll
        for (int op = 0; op < 2; op++) {
            const char* g = (op == 0) ? (const char*)Ahi : (const char*)Bhi;
            const int rb = (op == 0) ? mBase : nBase;
            const char* gbase = g + (size_t)rb * 1024 + (size_t)c * 128;
#pragma unroll
            for (int i = 0; i < 4; i++) {
                int idx = tid + i * 256;          // 0..1023
                int r = idx >> 3, q = idx & 7;
                uint32_t bo = (uint32_t)(r * 128 + q * 16);
                cp16(sb + op * 16384 + sw128(bo),
                     gbase + (size_t)r * 1024 + q * 16);
            }
        }
    };

    // prologue: chunks 0,1 into stages 0,1
#pragma unroll
    for (int c = 0; c < 2; c++) {
        load_stage(c, c);
        cp_commit();
    }

    // fragment-address components (verified mapping from R9)
    const int rowA = ((lane >> 3) & 1) * 8 + (lane & 7);
    const int khA  = lane >> 4;                // 0/1 -> k-half
    const int rowB = ((lane >> 4) & 1) * 8 + (lane & 7);
    const int khB  = (lane >> 3) & 1;

    for (int c = 0; c < NCHUNK; c++) {
        // wait until chunk c's group has landed
        if (c + 1 < NCHUNK) cp_wait<1>();
        else                cp_wait<0>();
        __syncthreads();   // stage c visible; stage (c+2)%3 free
        if (c + 2 < NCHUNK) {
            load_stage((c + 2) % NSTAGE, c + 2);
            cp_commit();
        }

        uint32_t sb = sbase + (c % NSTAGE) * STAGE_BYTES;
#pragma unroll
        for (int k16 = 0; k16 < 4; k16++) {
            uint32_t ah[2][4];
#pragma unroll
            for (int mt = 0; mt < 2; mt++) {
                int m0 = warpM * 32 + mt * 16;
                uint32_t bo = (uint32_t)((m0 + rowA) * 128 + k16 * 32 + khA * 16);
                ldm_x4(ah[mt], sb + ST_AH + sw128(bo));
            }
#pragma unroll
            for (int np = 0; np < 4; np++) {
                int n0 = warpN * 64 + np * 16;
                uint32_t bo = (uint32_t)((n0 + rowB) * 128 + k16 * 32 + khB * 16);
                uint32_t bh[4];
                ldm_x4(bh, sb + ST_BH + sw128(bo));
#pragma unroll
                for (int j = 0; j < 2; j++)
#pragma unroll
                    for (int mt = 0; mt < 2; mt++)
                        mma16816(acc[mt][np * 2 + j], ah[mt], &bh[2 * j]);
            }
        }
    }

    // ---- epilogue: acc fragment -> gmem ----
    const int r0  = mBase + warpM * 32 + (lane >> 2);
    const int c00 = nBase + warpN * 64 + 2 * (lane & 3);
#pragma unroll
    for (int mt = 0; mt < 2; mt++) {
#pragma unroll
        for (int nt = 0; nt < 8; nt++) {
            int row = r0 + mt * 16;
            int col = c00 + nt * 8;
            float2 v0 = make_float2(acc[mt][nt][0], acc[mt][nt][1]);
            float2 v1 = make_float2(acc[mt][nt][2], acc[mt][nt][3]);
            if (EPI) {
                float2 dv = *(const float2*)(Dv + col);
                float2 u0 = *(const float2*)(U + (size_t)row * 512 + col);
                float2 u1 = *(const float2*)(U + (size_t)(row + 8) * 512 + col);
                v0.x = fmaf(dv.x, u0.x, v0.x); v0.y = fmaf(dv.y, u0.y, v0.y);
                v1.x = fmaf(dv.x, u1.x, v1.x); v1.y = fmaf(dv.y, u1.y, v1.y);
            } else {
                v0.x *= W1_SCALE_INV; v0.y *= W1_SCALE_INV;
                v1.x *= W1_SCALE_INV; v1.y *= W1_SCALE_INV;
            }
            *(float2*)(Out + (size_t)row * 512 + col) = v0;
            *(float2*)(Out + (size_t)(row + 8) * 512 + col) = v1;
        }
    }
}

// -------------------- scan (verified fp32 path) ----------------------------
__global__ void k_scan_end() {
    int g = blockIdx.x * 256 + threadIdx.x;
    int p = g & (PDIM - 1);
    int c = (g >> 8) & (NCH - 1);
    int b = g >> 14;
    float2 a = g_lambda[p];
    float2 e = make_float2(0.0f, 0.0f);
    const float2* src = g_Bu + ((size_t)(b * LDIM + c * TCH)) * PDIM + p;
#pragma unroll 4
    for (int j = 0; j < TCH; j++) e = cfma(a, e, src[(size_t)j * PDIM]);
    g_end[(b * NCH + c) * PDIM + p] = e;
}

__global__ void k_scan_carry() {
    int g = blockIdx.x * 256 + threadIdx.x;
    int p = g & (PDIM - 1);
    int b = g >> 8;
    float2 aT = g_aT[p];
    float2 carry = make_float2(0.0f, 0.0f);
    for (int c = 0; c < NCH; c++) {
        g_carry[(b * NCH + c) * PDIM + p] = carry;
        float2 e = g_end[(b * NCH + c) * PDIM + p];
        carry = cfma(aT, carry, e);
    }
}

// phase C: rescan with carry; emit xs as fp16 + state
template <int STATE_MODE>
__global__ void k_scan_write(float* __restrict__ out_state) {
    int g = blockIdx.x * 256 + threadIdx.x;
    int p = g & (PDIM - 1);
    int c = (g >> 8) & (NCH - 1);
    int b = g >> 14;
    float2 a = g_lambda[p];
    float2 x = g_carry[(b * NCH + c) * PDIM + p];
    const size_t base = ((size_t)(b * LDIM + c * TCH)) * PDIM + p;
    const float2* buf = g_Bu + base;
    __half2* xh = (__half2*)g_Xhi + base;
#pragma unroll 4
    for (int j = 0; j < TCH; j++) {
        x = cfma(a, x, buf[(size_t)j * PDIM]);
        __half2 h;
        h.x = __float2half(x.x);
        h.y = __float2half(x.y);
        xh[(size_t)j * PDIM] = h;
    }
    if (c == NCH - 1) {
        if (STATE_MODE == 0) {
            out_state[b * PDIM + p] = x.x;
        } else {
            out_state[b * PDIM + p] = x.x;
            out_state[BDIM * PDIM + b * PDIM + p] = x.y;
        }
    }
}

// ---------------------------------------------------------------------------
extern "C" void kernel_launch(void* const* d_in, const int* in_sizes, int n_in,
                              void* d_out, int out_size) {
    const float* u   = (const float*)d_in[0];
    const float* Lre = (const float*)d_in[1];
    const float* Lim = (const float*)d_in[2];
    const float* Bw  = (const float*)d_in[3];
    const float* Cw  = (const float*)d_in[4];
    const float* Dv  = (const float*)d_in[5];
    const float* lst = (const float*)d_in[6];
    float* out = (float*)d_out;
    float* out_state = out + OUT_ELEMS;
    const long long state_floats = (long long)out_size - (long long)OUT_ELEMS;
    (void)in_sizes; (void)n_in;

    cudaFuncSetAttribute(k_mma_gemm<0>, cudaFuncAttributeMaxDynamicSharedMemorySize, GEMM_SMEM);
    cudaFuncSetAttribute(k_mma_gemm<1>, cudaFuncAttributeMaxDynamicSharedMemorySize, GEMM_SMEM);

    k_setup_small<<<1, 256>>>(Lre, Lim, lst);
    k_setup_weights<<<1024, 256>>>(Bw, Cw);
    k_split_u<<<16384, 256>>>(u);

    dim3 ggrid(4, BL / 128);   // (N tiles, M tiles) = (4, 256)
    k_mma_gemm<0><<<ggrid, 256, GEMM_SMEM>>>(nullptr, nullptr, nullptr);

    k_scan_end<<<(BDIM * NCH * PDIM) / 256, 256>>>();
    k_scan_carry<<<(BDIM * PDIM) / 256, 256>>>();
    if (state_floats == BDIM * PDIM) {
        k_scan_write<0><<<(BDIM * NCH * PDIM) / 256, 256>>>(out_state);
    } else {
        k_scan_write<1><<<(BDIM * NCH * PDIM) / 256, 256>>>(out_state);
    }

    k_mma_gemm<1><<<ggrid, 256, GEMM_SMEM>>>(out, u, Dv);
}